// round 14
// baseline (speedup 1.0000x reference)
#include <cuda_runtime.h>

#define TPB    256
#define IPT    4            // consecutive sorted ranks per thread
#define WIN    1024         // i-window granularity
#define SLICE  128          // ranks per warp slice (WIN / NWARP)
#define JCH    256          // j-chunk width
#define MAXN   16384
#define NWARP  (TPB / 32)

// Device-global state. Statically zero on first (correctness) call; the
// finalizing block resets accumulators each launch -> identical per replay.
__device__ unsigned long long g_C = 0ull, g_T = 0ull;
__device__ unsigned int g_M = 0u, g_done = 0u;
__device__ float2 g_is[MAXN];   // i windows, approx-sorted by y asc (balance only)
__device__ float2 g_jc[MAXN];   // j chunks: status==1 compacted, EXACT-sorted by y, +inf pad

__device__ __forceinline__ float pos_inf() { return __int_as_float(0x7f800000); }
__device__ __forceinline__ float neg_inf() { return __int_as_float(0xff800000); }

// 2-op accumulate: c += (yh >= b)
__device__ __forceinline__ void acc_ge(unsigned int& c, float yhv, float b) {
    asm volatile("{\n\t.reg .pred p;\n\t"
                 "setp.ge.f32 p, %1, %2;\n\t"
                 "@p add.u32 %0, %0, 1;\n\t}"
                 : "+r"(c) : "f"(yhv), "f"(b));
}
// 3-op guarded accumulate: c += (jj < len) && (yh >= b)
__device__ __forceinline__ void acc_ge_lt(unsigned int& c, int jj, int len,
                                          float yhv, float b) {
    asm volatile("{\n\t.reg .pred p, q;\n\t"
                 "setp.lt.s32 p, %1, %2;\n\t"
                 "setp.ge.and.f32 q, %3, %4, p;\n\t"
                 "@q add.u32 %0, %0, 1;\n\t}"
                 : "+r"(c) : "r"(jj), "r"(len), "f"(yhv), "f"(b));
}

// monotone 8-bit key from float (ascending)
__device__ __forceinline__ unsigned int key8(float f) {
    unsigned int u = __float_as_uint(f);
    u = (u >> 31) ? ~u : (u | 0x80000000u);
    return u >> 24;
}

union PrepSmem {
    struct {                               // i-window counting sort
        float2 sorted[WIN];                // 8KB
        unsigned int hist[256];
        unsigned int wsum[NWARP];
    } is;
    struct {                               // j-chunk rank sort
        float vy[JCH];
        float2 sorted[JCH];
    } js;
};

// ---------------------------------------------------------------------------
// Prep: blocks [0, iwins) approx-sort i-windows (counting sort on key8);
//       blocks [iwins, iwins+jchunks) compact + exact rank-sort j-chunks.
// ---------------------------------------------------------------------------
__global__ void __launch_bounds__(TPB)
prep_kernel(const float* __restrict__ y, const float* __restrict__ yh,
            const int* __restrict__ status, int n, int iwins) {
    __shared__ PrepSmem sm;
    const int tid = threadIdx.x;
    const int wid = tid >> 5, lid = tid & 31;
    const int b = (int)blockIdx.x;

    if (b < iwins) {
        const int base = b * WIN;
        float yv[IPT], yhv[IPT];
        unsigned int ky[IPT];
#pragma unroll
        for (int k = 0; k < IPT; k++) {
            int i = base + tid + k * TPB;
            bool v = (i < n);
            yv[k]  = v ? y[i]  : neg_inf();   // pad i -> len 0
            yhv[k] = v ? yh[i] : neg_inf();
            ky[k]  = key8(yv[k]);
        }
        sm.is.hist[tid] = 0u;
        __syncthreads();
#pragma unroll
        for (int k = 0; k < IPT; k++) atomicAdd(&sm.is.hist[ky[k]], 1u);
        __syncthreads();
        unsigned int cnt = sm.is.hist[tid];
        unsigned int incl = cnt;
#pragma unroll
        for (int off = 1; off < 32; off <<= 1) {
            unsigned int nb = __shfl_up_sync(0xffffffffu, incl, off);
            if (lid >= off) incl += nb;
        }
        if (lid == 31) sm.is.wsum[wid] = incl;
        __syncthreads();
        unsigned int wbase = 0;
#pragma unroll
        for (int w = 0; w < NWARP; w++) wbase += (w < wid) ? sm.is.wsum[w] : 0u;
        sm.is.hist[tid] = wbase + incl - cnt;
        __syncthreads();
#pragma unroll
        for (int k = 0; k < IPT; k++) {
            unsigned int pos = atomicAdd(&sm.is.hist[ky[k]], 1u);
            sm.is.sorted[pos] = make_float2(yv[k], yhv[k]);
        }
        __syncthreads();
        for (int e = tid; e < WIN; e += TPB) g_is[base + e] = sm.is.sorted[e];
    } else {
        const int c = b - iwins;
        const int j = c * JCH + tid;
        const bool jv = (j < n);
        float yj  = jv ? y[j]  : 0.0f;
        float yhj = jv ? yh[j] : 0.0f;
        const bool keep = jv && (status[j] == 1);
        const float val = keep ? yj : pos_inf();
        sm.js.vy[tid] = val;
        unsigned int bal = __ballot_sync(0xffffffffu, keep);
        if (lid == 0 && bal) atomicAdd(&g_M, (unsigned int)__popc(bal));
        __syncthreads();
        int rank = 0;
        const float4* vy4 = reinterpret_cast<const float4*>(sm.js.vy);
#pragma unroll 4
        for (int q = 0; q < JCH / 4; q++) {
            float4 o = vy4[q];
            int k0 = q * 4;
            rank += (o.x < val) || (o.x == val && (k0 + 0) < tid);
            rank += (o.y < val) || (o.y == val && (k0 + 1) < tid);
            rank += (o.z < val) || (o.z == val && (k0 + 2) < tid);
            rank += (o.w < val) || (o.w == val && (k0 + 3) < tid);
        }
        sm.js.sorted[rank] = make_float2(val, keep ? yhj : pos_inf());
        __syncthreads();
        g_jc[c * JCH + tid] = sm.js.sorted[tid];
    }
}

// ---------------------------------------------------------------------------
// Pair kernel. Block = (window-pair p, j-chunk jy). Warp w processes
// rank-slice w of window A=p and rank-slice (NWARP-1-w) of window B=iwins-1-p.
// Slice quantiles are complementary -> every warp's scan work ~ mjc (uniform).
//   T += prefix length (binary search in exact-sorted syc)
//   C += yh-condition over the prefix (yc implied), float4 bulk + guarded tail
// ---------------------------------------------------------------------------
__global__ void __launch_bounds__(TPB, 6)
pair_kernel(float* __restrict__ out, int iwins, int npair) {
    __shared__ float syc[JCH];
    __shared__ float syh[JCH];
    __shared__ unsigned long long sred[NWARP];

    const int tid = threadIdx.x;
    const int wid = tid >> 5, lid = tid & 31;
    const int p  = (int)blockIdx.x;
    const int jy = (int)blockIdx.y;
    const int wA = p;
    const int wB = iwins - 1 - p;

    float2 vj = g_jc[jy * JCH + tid];
    syc[tid] = vj.x;
    syh[tid] = vj.y;
    __syncthreads();

    unsigned int tcnt = 0u, ccnt = 0u;
    const float4* syh4 = reinterpret_cast<const float4*>(syh);

#pragma unroll
    for (int pass = 0; pass < 2; pass++) {
        if (pass && wB == wA) break;           // odd middle window: single pass
        const int win   = pass ? wB : wA;
        const int slice = pass ? (NWARP - 1 - wid) : wid;
        const int ib = win * WIN + slice * SLICE + lid * IPT;

        float yi[IPT], yhi[IPT];
#pragma unroll
        for (int k = 0; k < IPT; k++) {
            float2 a = g_is[ib + k];
            yi[k] = a.x; yhi[k] = a.y;
        }

        // exact prefix lengths: #{j : yc_j <= y_i}; T += len
        int len[IPT];
#pragma unroll
        for (int k = 0; k < IPT; k++) {
            int l = 0;
#pragma unroll
            for (int s = 128; s; s >>= 1)
                if (syc[l + s - 1] <= yi[k]) l += s;
            len[k] = l;
            tcnt += (unsigned int)l;
        }
        int lmin = min(min(len[0], len[1]), min(len[2], len[3]));
        int lmax = max(max(len[0], len[1]), max(len[2], len[3]));

        // bulk: 1 LDS.128 + 16 pred-ops per 16 pairs (yc implied by prefix)
        int nb4 = lmin >> 2;
        for (int q = 0; q < nb4; q++) {
            float4 b4 = syh4[q];
#pragma unroll
            for (int k = 0; k < IPT; k++) {
                acc_ge(ccnt, yhi[k], b4.x);
                acc_ge(ccnt, yhi[k], b4.y);
                acc_ge(ccnt, yhi[k], b4.z);
                acc_ge(ccnt, yhi[k], b4.w);
            }
        }
        // tail: remainder + per-i spread, guarded by len[k]
        for (int jj = nb4 << 2; jj < lmax; jj++) {
            float bb = syh[jj];
#pragma unroll
            for (int k = 0; k < IPT; k++)
                acc_ge_lt(ccnt, jj, len[k], yhi[k], bb);
        }
    }

    // warp reduce, pack (t<<32 | c): block sums < 2^21, no carry
#pragma unroll
    for (int off = 16; off; off >>= 1) {
        tcnt += __shfl_down_sync(0xffffffffu, tcnt, off);
        ccnt += __shfl_down_sync(0xffffffffu, ccnt, off);
    }
    if (lid == 0)
        sred[wid] = ((unsigned long long)tcnt << 32) | (unsigned long long)ccnt;
    __syncthreads();

    if (tid == 0) {
        unsigned long long s = 0ull;
#pragma unroll
        for (int w = 0; w < NWARP; w++) s += sred[w];
        atomicAdd(&g_T, s >> 32);
        atomicAdd(&g_C, s & 0xffffffffull);
        __threadfence();
        unsigned int old = atomicAdd(&g_done, 1u);
        if (old == (unsigned int)(npair - 1)) {
            __threadfence();
            double M = (double)atomicAdd(&g_M, 0u);
            double c = (double)atomicAdd(&g_C, 0ull) - M;   // drop diagonal
            double t = (double)atomicAdd(&g_T, 0ull) - M;
            out[0] = (float)(c / t);
            // reset for next graph replay
            g_C = 0ull; g_T = 0ull; g_M = 0u; g_done = 0u;
        }
    }
}

extern "C" void kernel_launch(void* const* d_in, const int* in_sizes, int n_in,
                              void* d_out, int out_size) {
    const float* y      = (const float*)d_in[0];
    const float* yh     = (const float*)d_in[1];
    const int*   status = (const int*)d_in[2];
    int n = in_sizes[0];

    int iwins   = (n + WIN - 1) / WIN;     // 16
    int jchunks = (n + JCH - 1) / JCH;     // 64
    int npairs  = (iwins + 1) / 2;         // 8
    int npair   = npairs * jchunks;        // 512

    prep_kernel<<<iwins + jchunks, TPB>>>(y, yh, status, n, iwins);

    dim3 grid(npairs, jchunks);
    pair_kernel<<<grid, TPB>>>((float*)d_out, iwins, npair);
}

// round 15
// speedup vs baseline: 1.9000x; 1.9000x over previous
#include <cuda_runtime.h>

#define TPB    256
#define IPT    4            // consecutive sorted ranks per thread
#define WIN    1024         // i-window granularity
#define SLICE  128          // ranks per warp slice (WIN / NWARP)
#define JCH    256          // j-chunk width
#define MAXN   16384
#define NWARP  (TPB / 32)

// Device-global state. Statically zero on first (correctness) call; the
// finalizing block resets accumulators each launch -> identical per replay.
__device__ unsigned long long g_C = 0ull, g_T = 0ull;
__device__ unsigned int g_M = 0u, g_done = 0u;
__device__ float2 g_is[MAXN];   // i windows, approx-sorted by y asc (balance only)
__device__ float2 g_jc[MAXN];   // j chunks: status==1 compacted, EXACT-sorted by y, +inf pad

__device__ __forceinline__ float pos_inf() { return __int_as_float(0x7f800000); }
__device__ __forceinline__ float neg_inf() { return __int_as_float(0xff800000); }

// 2-op accumulate: c += (yh >= b)
__device__ __forceinline__ void acc_ge(unsigned int& c, float yhv, float b) {
    asm volatile("{\n\t.reg .pred p;\n\t"
                 "setp.ge.f32 p, %1, %2;\n\t"
                 "@p add.u32 %0, %0, 1;\n\t}"
                 : "+r"(c) : "f"(yhv), "f"(b));
}
// 3-op guarded accumulate: c += (jj < len) && (yh >= b)
__device__ __forceinline__ void acc_ge_lt(unsigned int& c, int jj, int len,
                                          float yhv, float b) {
    asm volatile("{\n\t.reg .pred p, q;\n\t"
                 "setp.lt.s32 p, %1, %2;\n\t"
                 "setp.ge.and.f32 q, %3, %4, p;\n\t"
                 "@q add.u32 %0, %0, 1;\n\t}"
                 : "+r"(c) : "r"(jj), "r"(len), "f"(yhv), "f"(b));
}

// Monotone (non-strict) 8-bit key matched to ~N(0,1) data: linear quantization
// over [-4, 4]. ~256 effective bins of width 0.031 -> rank jitter ~+-13.
// Clamp-before-cast makes -inf padding safe (key 0). Approximate order only
// affects load balance / tail length, never correctness.
__device__ __forceinline__ unsigned int key8(float f) {
    float t = fminf(fmaxf((f + 4.0f) * 32.0f, 0.0f), 255.0f);
    return (unsigned int)t;
}

union PrepSmem {
    struct {                               // i-window counting sort
        float2 sorted[WIN];                // 8KB
        unsigned int hist[256];
        unsigned int wsum[NWARP];
    } is;
    struct {                               // j-chunk rank sort
        float vy[JCH];
        float2 sorted[JCH];
    } js;
};

// ---------------------------------------------------------------------------
// Prep: blocks [0, iwins) approx-sort i-windows (counting sort on key8);
//       blocks [iwins, iwins+jchunks) compact + exact rank-sort j-chunks.
// ---------------------------------------------------------------------------
__global__ void __launch_bounds__(TPB)
prep_kernel(const float* __restrict__ y, const float* __restrict__ yh,
            const int* __restrict__ status, int n, int iwins) {
    __shared__ PrepSmem sm;
    const int tid = threadIdx.x;
    const int wid = tid >> 5, lid = tid & 31;
    const int b = (int)blockIdx.x;

    if (b < iwins) {
        const int base = b * WIN;
        float yv[IPT], yhv[IPT];
        unsigned int ky[IPT];
#pragma unroll
        for (int k = 0; k < IPT; k++) {
            int i = base + tid + k * TPB;
            bool v = (i < n);
            yv[k]  = v ? y[i]  : neg_inf();   // pad i -> len 0
            yhv[k] = v ? yh[i] : neg_inf();
            ky[k]  = key8(yv[k]);
        }
        sm.is.hist[tid] = 0u;
        __syncthreads();
#pragma unroll
        for (int k = 0; k < IPT; k++) atomicAdd(&sm.is.hist[ky[k]], 1u);
        __syncthreads();
        unsigned int cnt = sm.is.hist[tid];
        unsigned int incl = cnt;
#pragma unroll
        for (int off = 1; off < 32; off <<= 1) {
            unsigned int nb = __shfl_up_sync(0xffffffffu, incl, off);
            if (lid >= off) incl += nb;
        }
        if (lid == 31) sm.is.wsum[wid] = incl;
        __syncthreads();
        unsigned int wbase = 0;
#pragma unroll
        for (int w = 0; w < NWARP; w++) wbase += (w < wid) ? sm.is.wsum[w] : 0u;
        sm.is.hist[tid] = wbase + incl - cnt;   // exclusive bin offset
        __syncthreads();
#pragma unroll
        for (int k = 0; k < IPT; k++) {
            unsigned int pos = atomicAdd(&sm.is.hist[ky[k]], 1u);
            sm.is.sorted[pos] = make_float2(yv[k], yhv[k]);
        }
        __syncthreads();
        for (int e = tid; e < WIN; e += TPB) g_is[base + e] = sm.is.sorted[e];
    } else {
        const int c = b - iwins;
        const int j = c * JCH + tid;
        const bool jv = (j < n);
        float yj  = jv ? y[j]  : 0.0f;
        float yhj = jv ? yh[j] : 0.0f;
        const bool keep = jv && (status[j] == 1);
        const float val = keep ? yj : pos_inf();
        sm.js.vy[tid] = val;
        unsigned int bal = __ballot_sync(0xffffffffu, keep);
        if (lid == 0 && bal) atomicAdd(&g_M, (unsigned int)__popc(bal));
        __syncthreads();
        int rank = 0;
        const float4* vy4 = reinterpret_cast<const float4*>(sm.js.vy);
#pragma unroll 4
        for (int q = 0; q < JCH / 4; q++) {
            float4 o = vy4[q];
            int k0 = q * 4;
            rank += (o.x < val) || (o.x == val && (k0 + 0) < tid);
            rank += (o.y < val) || (o.y == val && (k0 + 1) < tid);
            rank += (o.z < val) || (o.z == val && (k0 + 2) < tid);
            rank += (o.w < val) || (o.w == val && (k0 + 3) < tid);
        }
        sm.js.sorted[rank] = make_float2(val, keep ? yhj : pos_inf());
        __syncthreads();
        g_jc[c * JCH + tid] = sm.js.sorted[tid];
    }
}

// ---------------------------------------------------------------------------
// Pair kernel. Block = (window-pair p, j-chunk jy). Warp w processes
// rank-slice w of window A=p and rank-slice (NWARP-1-w) of window B=iwins-1-p.
// Slice quantiles are complementary -> every warp's scan work ~ mjc (uniform).
//   T += prefix length (binary search in exact-sorted syc)
//   C += yh-condition over the prefix (yc implied), float4 bulk + guarded tail
// ---------------------------------------------------------------------------
__global__ void __launch_bounds__(TPB, 6)
pair_kernel(float* __restrict__ out, int iwins, int npair) {
    __shared__ float syc[JCH];
    __shared__ float syh[JCH];
    __shared__ unsigned long long sred[NWARP];

    const int tid = threadIdx.x;
    const int wid = tid >> 5, lid = tid & 31;
    const int p  = (int)blockIdx.x;
    const int jy = (int)blockIdx.y;
    const int wA = p;
    const int wB = iwins - 1 - p;

    float2 vj = g_jc[jy * JCH + tid];
    syc[tid] = vj.x;
    syh[tid] = vj.y;
    __syncthreads();

    unsigned int tcnt = 0u, ccnt = 0u;
    const float4* syh4 = reinterpret_cast<const float4*>(syh);

#pragma unroll
    for (int pass = 0; pass < 2; pass++) {
        if (pass && wB == wA) break;           // odd middle window: single pass
        const int win   = pass ? wB : wA;
        const int slice = pass ? (NWARP - 1 - wid) : wid;
        const int ib = win * WIN + slice * SLICE + lid * IPT;

        float yi[IPT], yhi[IPT];
#pragma unroll
        for (int k = 0; k < IPT; k++) {
            float2 a = g_is[ib + k];
            yi[k] = a.x; yhi[k] = a.y;
        }

        // exact prefix lengths: #{j : yc_j <= y_i}; T += len
        int len[IPT];
#pragma unroll
        for (int k = 0; k < IPT; k++) {
            int l = 0;
#pragma unroll
            for (int s = 128; s; s >>= 1)
                if (syc[l + s - 1] <= yi[k]) l += s;
            len[k] = l;
            tcnt += (unsigned int)l;
        }
        int lmin = min(min(len[0], len[1]), min(len[2], len[3]));
        int lmax = max(max(len[0], len[1]), max(len[2], len[3]));

        // bulk: 1 LDS.128 + 16 pred-ops per 16 pairs (yc implied by prefix)
        int nb4 = lmin >> 2;
        for (int q = 0; q < nb4; q++) {
            float4 b4 = syh4[q];
#pragma unroll
            for (int k = 0; k < IPT; k++) {
                acc_ge(ccnt, yhi[k], b4.x);
                acc_ge(ccnt, yhi[k], b4.y);
                acc_ge(ccnt, yhi[k], b4.z);
                acc_ge(ccnt, yhi[k], b4.w);
            }
        }
        // tail: remainder + per-i spread, guarded by len[k]
        for (int jj = nb4 << 2; jj < lmax; jj++) {
            float bb = syh[jj];
#pragma unroll
            for (int k = 0; k < IPT; k++)
                acc_ge_lt(ccnt, jj, len[k], yhi[k], bb);
        }
    }

    // warp reduce, pack (t<<32 | c): block sums < 2^21, no carry
#pragma unroll
    for (int off = 16; off; off >>= 1) {
        tcnt += __shfl_down_sync(0xffffffffu, tcnt, off);
        ccnt += __shfl_down_sync(0xffffffffu, ccnt, off);
    }
    if (lid == 0)
        sred[wid] = ((unsigned long long)tcnt << 32) | (unsigned long long)ccnt;
    __syncthreads();

    if (tid == 0) {
        unsigned long long s = 0ull;
#pragma unroll
        for (int w = 0; w < NWARP; w++) s += sred[w];
        atomicAdd(&g_T, s >> 32);
        atomicAdd(&g_C, s & 0xffffffffull);
        __threadfence();
        unsigned int old = atomicAdd(&g_done, 1u);
        if (old == (unsigned int)(npair - 1)) {
            __threadfence();
            double M = (double)atomicAdd(&g_M, 0u);
            double c = (double)atomicAdd(&g_C, 0ull) - M;   // drop diagonal
            double t = (double)atomicAdd(&g_T, 0ull) - M;
            out[0] = (float)(c / t);
            // reset for next graph replay
            g_C = 0ull; g_T = 0ull; g_M = 0u; g_done = 0u;
        }
    }
}

extern "C" void kernel_launch(void* const* d_in, const int* in_sizes, int n_in,
                              void* d_out, int out_size) {
    const float* y      = (const float*)d_in[0];
    const float* yh     = (const float*)d_in[1];
    const int*   status = (const int*)d_in[2];
    int n = in_sizes[0];

    int iwins   = (n + WIN - 1) / WIN;     // 16
    int jchunks = (n + JCH - 1) / JCH;     // 64
    int npairs  = (iwins + 1) / 2;         // 8
    int npair   = npairs * jchunks;        // 512

    prep_kernel<<<iwins + jchunks, TPB>>>(y, yh, status, n, iwins);

    dim3 grid(npairs, jchunks);
    pair_kernel<<<grid, TPB>>>((float*)d_out, iwins, npair);
}

// round 16
// speedup vs baseline: 2.1308x; 1.1215x over previous
#include <cuda_runtime.h>

#define TPB    256          // prep block size
#define PTPB   128          // pair block size (4 warps)
#define IPT    4            // consecutive sorted ranks per thread
#define WIN    1024         // i-window granularity
#define SLICE  128          // ranks per warp slice (WIN / 8 slices)
#define JCH    256          // j-chunk width
#define MAXN   16384
#define NWARP  (TPB / 32)   // prep warps
#define PW     (PTPB / 32)  // pair warps per block

// Device-global state. Statically zero on first (correctness) call; the
// finalizing block resets accumulators each launch -> identical per replay.
__device__ unsigned long long g_C = 0ull, g_T = 0ull;
__device__ unsigned int g_M = 0u, g_done = 0u;
__device__ float2 g_is[MAXN];   // i windows, approx-sorted by y asc (balance only)
__device__ float2 g_jc[MAXN];   // j chunks: status==1 compacted, EXACT-sorted by y, +inf pad

__device__ __forceinline__ float pos_inf() { return __int_as_float(0x7f800000); }
__device__ __forceinline__ float neg_inf() { return __int_as_float(0xff800000); }

// 2-op accumulate: c += (yh >= b). Non-volatile: pure register computation.
__device__ __forceinline__ void acc_ge(unsigned int& c, float yhv, float b) {
    asm("{\n\t.reg .pred p;\n\t"
        "setp.ge.f32 p, %1, %2;\n\t"
        "@p add.u32 %0, %0, 1;\n\t}"
        : "+r"(c) : "f"(yhv), "f"(b));
}
// 3-op guarded accumulate: c += (jj < len) && (yh >= b)
__device__ __forceinline__ void acc_ge_lt(unsigned int& c, int jj, int len,
                                          float yhv, float b) {
    asm("{\n\t.reg .pred p, q;\n\t"
        "setp.lt.s32 p, %1, %2;\n\t"
        "setp.ge.and.f32 q, %3, %4, p;\n\t"
        "@q add.u32 %0, %0, 1;\n\t}"
        : "+r"(c) : "r"(jj), "r"(len), "f"(yhv), "f"(b));
}

// Monotone (non-strict) 8-bit key matched to ~N(0,1) data: linear quantization
// over [-4, 4]. Clamp-before-cast makes -inf padding safe (key 0). Approximate
// order only affects load balance / tail length, never correctness.
__device__ __forceinline__ unsigned int key8(float f) {
    float t = fminf(fmaxf((f + 4.0f) * 32.0f, 0.0f), 255.0f);
    return (unsigned int)t;
}

union PrepSmem {
    struct {                               // i-window counting sort
        float2 sorted[WIN];                // 8KB
        unsigned int hist[256];
        unsigned int wsum[NWARP];
    } is;
    struct {                               // j-chunk rank sort
        float vy[JCH];
        float2 sorted[JCH];
    } js;
};

// ---------------------------------------------------------------------------
// Prep: blocks [0, iwins) approx-sort i-windows (counting sort on key8);
//       blocks [iwins, iwins+jchunks) compact + exact rank-sort j-chunks.
// ---------------------------------------------------------------------------
__global__ void __launch_bounds__(TPB)
prep_kernel(const float* __restrict__ y, const float* __restrict__ yh,
            const int* __restrict__ status, int n, int iwins) {
    __shared__ PrepSmem sm;
    const int tid = threadIdx.x;
    const int wid = tid >> 5, lid = tid & 31;
    const int b = (int)blockIdx.x;

    if (b < iwins) {
        const int base = b * WIN;
        float yv[IPT], yhv[IPT];
        unsigned int ky[IPT];
#pragma unroll
        for (int k = 0; k < IPT; k++) {
            int i = base + tid + k * TPB;
            bool v = (i < n);
            yv[k]  = v ? y[i]  : neg_inf();   // pad i -> len 0
            yhv[k] = v ? yh[i] : neg_inf();
            ky[k]  = key8(yv[k]);
        }
        sm.is.hist[tid] = 0u;
        __syncthreads();
#pragma unroll
        for (int k = 0; k < IPT; k++) atomicAdd(&sm.is.hist[ky[k]], 1u);
        __syncthreads();
        unsigned int cnt = sm.is.hist[tid];
        unsigned int incl = cnt;
#pragma unroll
        for (int off = 1; off < 32; off <<= 1) {
            unsigned int nb = __shfl_up_sync(0xffffffffu, incl, off);
            if (lid >= off) incl += nb;
        }
        if (lid == 31) sm.is.wsum[wid] = incl;
        __syncthreads();
        unsigned int wbase = 0;
#pragma unroll
        for (int w = 0; w < NWARP; w++) wbase += (w < wid) ? sm.is.wsum[w] : 0u;
        sm.is.hist[tid] = wbase + incl - cnt;   // exclusive bin offset
        __syncthreads();
#pragma unroll
        for (int k = 0; k < IPT; k++) {
            unsigned int pos = atomicAdd(&sm.is.hist[ky[k]], 1u);
            sm.is.sorted[pos] = make_float2(yv[k], yhv[k]);
        }
        __syncthreads();
        for (int e = tid; e < WIN; e += TPB) g_is[base + e] = sm.is.sorted[e];
    } else {
        const int c = b - iwins;
        const int j = c * JCH + tid;
        const bool jv = (j < n);
        float yj  = jv ? y[j]  : 0.0f;
        float yhj = jv ? yh[j] : 0.0f;
        const bool keep = jv && (status[j] == 1);
        const float val = keep ? yj : pos_inf();
        sm.js.vy[tid] = val;
        unsigned int bal = __ballot_sync(0xffffffffu, keep);
        if (lid == 0 && bal) atomicAdd(&g_M, (unsigned int)__popc(bal));
        __syncthreads();
        int rank = 0;
        const float4* vy4 = reinterpret_cast<const float4*>(sm.js.vy);
#pragma unroll 4
        for (int q = 0; q < JCH / 4; q++) {
            float4 o = vy4[q];
            int k0 = q * 4;
            rank += (o.x < val) || (o.x == val && (k0 + 0) < tid);
            rank += (o.y < val) || (o.y == val && (k0 + 1) < tid);
            rank += (o.z < val) || (o.z == val && (k0 + 2) < tid);
            rank += (o.w < val) || (o.w == val && (k0 + 3) < tid);
        }
        sm.js.sorted[rank] = make_float2(val, keep ? yhj : pos_inf());
        __syncthreads();
        g_jc[c * JCH + tid] = sm.js.sorted[tid];
    }
}

// ---------------------------------------------------------------------------
// Pair kernel. Block = (window-pair p, j-chunk jy, half h). Warp w handles
// rank-slice (4h+w) of window A=p and rank-slice 7-(4h+w) of window B=iwins-1-p.
// Complementary quantiles -> every warp's scan work ~ mjc (uniform).
//   T += prefix length (binary search in exact-sorted syc)
//   C += yh-condition over the prefix (yc implied), float4 bulk + guarded tail
// Four independent C accumulators break the predicated-IADD RAW chain.
// ---------------------------------------------------------------------------
__global__ void __launch_bounds__(PTPB, 12)
pair_kernel(float* __restrict__ out, int iwins, int npair) {
    __shared__ float syc[JCH];
    __shared__ float syh[JCH];
    __shared__ unsigned long long sred[PW];

    const int tid = threadIdx.x;
    const int wid = tid >> 5, lid = tid & 31;
    const int p  = (int)blockIdx.x;
    const int jy = (int)blockIdx.y;
    const int h  = (int)blockIdx.z;
    const int wA = p;
    const int wB = iwins - 1 - p;
    const int sp = h * PW + wid;            // this warp's slice 0..7

    for (int e = tid; e < JCH; e += PTPB) {
        float2 vj = g_jc[jy * JCH + e];
        syc[e] = vj.x;
        syh[e] = vj.y;
    }
    __syncthreads();

    unsigned int tcnt = 0u;
    unsigned int c0 = 0u, c1 = 0u, c2 = 0u, c3 = 0u;
    const float4* syh4 = reinterpret_cast<const float4*>(syh);

#pragma unroll
    for (int pass = 0; pass < 2; pass++) {
        if (pass && wB == wA) break;        // odd middle window: single pass
        const int win   = pass ? wB : wA;
        const int slice = pass ? (7 - sp) : sp;
        const int ib = win * WIN + slice * SLICE + lid * IPT;

        float yi[IPT], yhi[IPT];
#pragma unroll
        for (int k = 0; k < IPT; k++) {
            float2 a = g_is[ib + k];
            yi[k] = a.x; yhi[k] = a.y;
        }

        // exact prefix lengths: #{j : yc_j <= y_i}; T += len (4-way ILP)
        int len[IPT];
#pragma unroll
        for (int k = 0; k < IPT; k++) {
            int l = 0;
#pragma unroll
            for (int s = 128; s; s >>= 1)
                if (syc[l + s - 1] <= yi[k]) l += s;
            len[k] = l;
            tcnt += (unsigned int)l;
        }
        int lmin = min(min(len[0], len[1]), min(len[2], len[3]));
        int lmax = max(max(len[0], len[1]), max(len[2], len[3]));

        // bulk: 1 LDS.128 + 32 pred-ops per 16 pairs, 4 independent add chains
        int nb4 = lmin >> 2;
#pragma unroll 2
        for (int q = 0; q < nb4; q++) {
            float4 b4 = syh4[q];
            acc_ge(c0, yhi[0], b4.x); acc_ge(c1, yhi[1], b4.x);
            acc_ge(c2, yhi[2], b4.x); acc_ge(c3, yhi[3], b4.x);
            acc_ge(c0, yhi[0], b4.y); acc_ge(c1, yhi[1], b4.y);
            acc_ge(c2, yhi[2], b4.y); acc_ge(c3, yhi[3], b4.y);
            acc_ge(c0, yhi[0], b4.z); acc_ge(c1, yhi[1], b4.z);
            acc_ge(c2, yhi[2], b4.z); acc_ge(c3, yhi[3], b4.z);
            acc_ge(c0, yhi[0], b4.w); acc_ge(c1, yhi[1], b4.w);
            acc_ge(c2, yhi[2], b4.w); acc_ge(c3, yhi[3], b4.w);
        }
        // tail: remainder + per-i spread, guarded by len[k]
        for (int jj = nb4 << 2; jj < lmax; jj++) {
            float bb = syh[jj];
            acc_ge_lt(c0, jj, len[0], yhi[0], bb);
            acc_ge_lt(c1, jj, len[1], yhi[1], bb);
            acc_ge_lt(c2, jj, len[2], yhi[2], bb);
            acc_ge_lt(c3, jj, len[3], yhi[3], bb);
        }
    }

    unsigned int ccnt = (c0 + c1) + (c2 + c3);

    // warp reduce, pack (t<<32 | c): block sums < 2^20, no carry
#pragma unroll
    for (int off = 16; off; off >>= 1) {
        tcnt += __shfl_down_sync(0xffffffffu, tcnt, off);
        ccnt += __shfl_down_sync(0xffffffffu, ccnt, off);
    }
    if (lid == 0)
        sred[wid] = ((unsigned long long)tcnt << 32) | (unsigned long long)ccnt;
    __syncthreads();

    if (tid == 0) {
        unsigned long long s = 0ull;
#pragma unroll
        for (int w = 0; w < PW; w++) s += sred[w];
        atomicAdd(&g_T, s >> 32);
        atomicAdd(&g_C, s & 0xffffffffull);
        __threadfence();
        unsigned int old = atomicAdd(&g_done, 1u);
        if (old == (unsigned int)(npair - 1)) {
            __threadfence();
            double M = (double)atomicAdd(&g_M, 0u);
            double c = (double)atomicAdd(&g_C, 0ull) - M;   // drop diagonal
            double t = (double)atomicAdd(&g_T, 0ull) - M;
            out[0] = (float)(c / t);
            // reset for next graph replay
            g_C = 0ull; g_T = 0ull; g_M = 0u; g_done = 0u;
        }
    }
}

extern "C" void kernel_launch(void* const* d_in, const int* in_sizes, int n_in,
                              void* d_out, int out_size) {
    const float* y      = (const float*)d_in[0];
    const float* yh     = (const float*)d_in[1];
    const int*   status = (const int*)d_in[2];
    int n = in_sizes[0];

    int iwins   = (n + WIN - 1) / WIN;     // 16
    int jchunks = (n + JCH - 1) / JCH;     // 64
    int npairs  = (iwins + 1) / 2;         // 8
    int npair   = npairs * jchunks * 2;    // 1024 blocks

    prep_kernel<<<iwins + jchunks, TPB>>>(y, yh, status, n, iwins);

    dim3 grid(npairs, jchunks, 2);
    pair_kernel<<<grid, PTPB>>>((float*)d_out, iwins, npair);
}